// round 2
// baseline (speedup 1.0000x reference)
#include <cuda_runtime.h>
#include <cstdint>

// W8A8 int8 GEMM: out[m][n] = alpha * sum_k x[m][k]*w[n][k] + bias[n]
// Harness delivers x/weight promoted to int32 (values in [-127,127]).
// Stage 1: pack int32 -> int8 into __device__ scratch.
// Stage 2: int8 tensor-core GEMM (mma.m16n8k32.s8) with fused dequant+bias epilogue.

namespace {
constexpr int Mtot = 8192;
constexpr int Ntot = 4096;
constexpr int Ktot = 4096;
constexpr int BM = 128;
constexpr int BN = 128;
constexpr int BK = 64;     // int8 elems along K per tile
constexpr int NTH = 256;   // 8 warps: 4 (M) x 2 (N)
}  // namespace

// 50 MB packed-int8 scratch (device globals: the sanctioned no-alloc scratch).
__device__ __align__(16) int8_t g_x8[(size_t)Mtot * Ktot];
__device__ __align__(16) int8_t g_w8[(size_t)Ntot * Ktot];

namespace {
// Swizzled shared layout: row-major [rows][64B], 16B chunks XOR-permuted by (row>>1)&3
// -> conflict-free ldmatrix (8 distinct 16B slots per 128B phase) and 16B-aligned cp.async.
__device__ __forceinline__ uint32_t swz(int row, int kbyte) {
    return (uint32_t)(row * BK + ((((kbyte >> 4) ^ ((row >> 1) & 3)) & 3) << 4) + (kbyte & 15));
}

__device__ __forceinline__ void cp_async16(uint32_t saddr, const void* gptr) {
    asm volatile("cp.async.cg.shared.global [%0], [%1], 16;\n" :: "r"(saddr), "l"(gptr));
}
__device__ __forceinline__ void cp_commit() {
    asm volatile("cp.async.commit_group;\n" ::);
}
__device__ __forceinline__ void cp_wait0() {
    asm volatile("cp.async.wait_group 0;\n" ::);
}

__device__ __forceinline__ void ldm4(uint32_t& r0, uint32_t& r1, uint32_t& r2, uint32_t& r3,
                                     uint32_t addr) {
    asm volatile("ldmatrix.sync.aligned.m8n8.x4.shared.b16 {%0,%1,%2,%3}, [%4];"
                 : "=r"(r0), "=r"(r1), "=r"(r2), "=r"(r3) : "r"(addr));
}

__device__ __forceinline__ void mma_s8(int32_t* d, const uint32_t* a, const uint32_t* b) {
    asm volatile("mma.sync.aligned.m16n8k32.row.col.s32.s8.s8.s32 "
                 "{%0,%1,%2,%3}, {%4,%5,%6,%7}, {%8,%9}, {%0,%1,%2,%3};"
                 : "+r"(d[0]), "+r"(d[1]), "+r"(d[2]), "+r"(d[3])
                 : "r"(a[0]), "r"(a[1]), "r"(a[2]), "r"(a[3]), "r"(b[0]), "r"(b[1]));
}

__device__ __forceinline__ uint32_t pack4(int4 v) {
    return (uint32_t)(v.x & 0xFF) | ((uint32_t)(v.y & 0xFF) << 8) |
           ((uint32_t)(v.z & 0xFF) << 16) | ((uint32_t)(v.w & 0xFF) << 24);
}
}  // namespace

// -------- Stage 1: int32 -> int8 pack (16 elems per thread) --------
__global__ void pack_x_kernel(const int* __restrict__ src, int n16) {
    int i = blockIdx.x * blockDim.x + threadIdx.x;
    if (i >= n16) return;
    const int4* s = reinterpret_cast<const int4*>(src) + (size_t)i * 4;
    int4 a = s[0], b = s[1], c = s[2], d = s[3];
    uint4 o = make_uint4(pack4(a), pack4(b), pack4(c), pack4(d));
    reinterpret_cast<uint4*>(g_x8)[i] = o;
}

__global__ void pack_w_kernel(const int* __restrict__ src, int n16) {
    int i = blockIdx.x * blockDim.x + threadIdx.x;
    if (i >= n16) return;
    const int4* s = reinterpret_cast<const int4*>(src) + (size_t)i * 4;
    int4 a = s[0], b = s[1], c = s[2], d = s[3];
    uint4 o = make_uint4(pack4(a), pack4(b), pack4(c), pack4(d));
    reinterpret_cast<uint4*>(g_w8)[i] = o;
}

// -------- Stage 2: int8 tensor-core GEMM --------
__global__ void __launch_bounds__(NTH, 2)
w8a8_gemm_kernel(const float* __restrict__ bias, const float* __restrict__ alphap,
                 float* __restrict__ out) {
    __shared__ __align__(128) int8_t sA[2][BM * BK];
    __shared__ __align__(128) int8_t sB[2][BN * BK];

    const int8_t* __restrict__ X = g_x8;
    const int8_t* __restrict__ W = g_w8;

    const int tid = threadIdx.x;
    const int lane = tid & 31;
    const int warp = tid >> 5;
    const int wm = warp >> 1;  // 0..3 -> 32 rows each
    const int wn = warp & 1;   // 0..1 -> 64 cols each

    const int bm = blockIdx.y * BM;
    const int bn = blockIdx.x * BN;

    const uint32_t sA_base = (uint32_t)__cvta_generic_to_shared(&sA[0][0]);
    const uint32_t sB_base = (uint32_t)__cvta_generic_to_shared(&sB[0][0]);

    // Global->shared: tile = 512 x 16B chunks; thread handles chunks tid, tid+256.
    const int rA0 = tid >> 2, kcA0 = tid & 3;
    const int rA1 = (tid + 256) >> 2, kcA1 = (tid + 256) & 3;

    // ldmatrix per-lane address components.
    const int l8 = lane & 7;
    const int g4 = lane >> 3;
    // A x4: g0:(rows0-7,k0) g1:(rows8-15,k0) g2:(rows0-7,k16) g3:(rows8-15,k16)
    const int aRowOff = ((g4 & 1) << 3) + l8;
    const int aKoff = (g4 >> 1) << 4;
    // B x4: g0:(n0-7,k0) g1:(n0-7,k16) g2:(n8-15,k0) g3:(n8-15,k16)
    const int bRowOff = ((g4 >> 1) << 3) + l8;
    const int bKoff = (g4 & 1) << 4;

    int32_t acc[2][8][4];
#pragma unroll
    for (int mt = 0; mt < 2; mt++)
#pragma unroll
        for (int nt = 0; nt < 8; nt++)
#pragma unroll
            for (int i = 0; i < 4; i++) acc[mt][nt][i] = 0;

    const int nkt = Ktot / BK;  // 64

    // ---- prologue: tile 0 -> buf 0 ----
    {
        cp_async16(sA_base + swz(rA0, kcA0 * 16), X + (size_t)(bm + rA0) * Ktot + kcA0 * 16);
        cp_async16(sA_base + swz(rA1, kcA1 * 16), X + (size_t)(bm + rA1) * Ktot + kcA1 * 16);
        cp_async16(sB_base + swz(rA0, kcA0 * 16), W + (size_t)(bn + rA0) * Ktot + kcA0 * 16);
        cp_async16(sB_base + swz(rA1, kcA1 * 16), W + (size_t)(bn + rA1) * Ktot + kcA1 * 16);
        cp_commit();
        cp_wait0();
        __syncthreads();
    }

    int buf = 0;
    for (int kt = 0; kt < nkt; kt++) {
        if (kt + 1 < nkt) {
            const int kbase = (kt + 1) * BK;
            const uint32_t sAo = sA_base + (buf ^ 1) * (BM * BK);
            const uint32_t sBo = sB_base + (buf ^ 1) * (BN * BK);
            cp_async16(sAo + swz(rA0, kcA0 * 16), X + (size_t)(bm + rA0) * Ktot + kbase + kcA0 * 16);
            cp_async16(sAo + swz(rA1, kcA1 * 16), X + (size_t)(bm + rA1) * Ktot + kbase + kcA1 * 16);
            cp_async16(sBo + swz(rA0, kcA0 * 16), W + (size_t)(bn + rA0) * Ktot + kbase + kcA0 * 16);
            cp_async16(sBo + swz(rA1, kcA1 * 16), W + (size_t)(bn + rA1) * Ktot + kbase + kcA1 * 16);
        }
        cp_commit();

        const uint32_t sAc = sA_base + buf * (BM * BK);
        const uint32_t sBc = sB_base + buf * (BN * BK);

#pragma unroll
        for (int ks = 0; ks < 2; ks++) {
            uint32_t a[2][4];
#pragma unroll
            for (int mt = 0; mt < 2; mt++) {
                const int row = wm * 32 + mt * 16 + aRowOff;
                ldm4(a[mt][0], a[mt][1], a[mt][2], a[mt][3],
                     sAc + swz(row, ks * 32 + aKoff));
            }
            uint32_t b[8][2];
#pragma unroll
            for (int p = 0; p < 4; p++) {
                const int row = wn * 64 + p * 16 + bRowOff;
                uint32_t r0, r1, r2, r3;
                ldm4(r0, r1, r2, r3, sBc + swz(row, ks * 32 + bKoff));
                b[2 * p][0] = r0;
                b[2 * p][1] = r1;
                b[2 * p + 1][0] = r2;
                b[2 * p + 1][1] = r3;
            }
#pragma unroll
            for (int mt = 0; mt < 2; mt++)
#pragma unroll
                for (int nt = 0; nt < 8; nt++)
                    mma_s8(acc[mt][nt], a[mt], b[nt]);
        }

        cp_wait0();
        __syncthreads();
        buf ^= 1;
    }

    // ---- epilogue: out = alpha*acc + bias ----
    const float alpha = alphap[0];
    const int g = lane >> 2;
    const int tig = lane & 3;

#pragma unroll
    for (int mt = 0; mt < 2; mt++) {
#pragma unroll
        for (int nt = 0; nt < 8; nt++) {
            const int row0 = bm + wm * 32 + mt * 16 + g;
            const int col = bn + wn * 64 + nt * 8 + tig * 2;
            const float b0 = bias[col];
            const float b1 = bias[col + 1];
            float2 v0, v1;
            v0.x = alpha * (float)acc[mt][nt][0] + b0;
            v0.y = alpha * (float)acc[mt][nt][1] + b1;
            v1.x = alpha * (float)acc[mt][nt][2] + b0;
            v1.y = alpha * (float)acc[mt][nt][3] + b1;
            *reinterpret_cast<float2*>(out + (size_t)row0 * Ntot + col) = v0;
            *reinterpret_cast<float2*>(out + (size_t)(row0 + 8) * Ntot + col) = v1;
        }
    }
}

extern "C" void kernel_launch(void* const* d_in, const int* in_sizes, int n_in,
                              void* d_out, int out_size) {
    const int* X32 = (const int*)d_in[0];
    const int* W32 = (const int*)d_in[1];
    const float* bias = (const float*)d_in[2];
    const float* alpha = (const float*)d_in[3];
    float* out = (float*)d_out;

    const int nx16 = (Mtot * Ktot) / 16;  // 2097152
    const int nw16 = (Ntot * Ktot) / 16;  // 1048576
    pack_x_kernel<<<(nx16 + 255) / 256, 256>>>(X32, nx16);
    pack_w_kernel<<<(nw16 + 255) / 256, 256>>>(W32, nw16);

    dim3 grid(Ntot / BN, Mtot / BM);  // (32, 64)
    w8a8_gemm_kernel<<<grid, NTH>>>(bias, alpha, out);
}